// round 1
// baseline (speedup 1.0000x reference)
#include <cuda_runtime.h>
#include <cuda_bf16.h>
#include <cstdint>

// Problem constants (fixed shapes from reference)
#define BB 4
#define TT 2048
#define CC 1024
#define HH 16
#define DD 64
#define MM (BB*TT)        // 8192

// Scratch buffers (device globals: allocation-free rule)
__device__ float g_qkv[(size_t)MM * 3 * CC];   // [8192, 3072]
__device__ float g_att[(size_t)MM * CC];       // [8192, 1024]

// ---------------------------------------------------------------------------
// SGEMM: C[M,N] = A[M,K] @ B[K,N] + bias[N]
// 128x128 block tile, BK=8, 256 threads, 8x8 per-thread microtile.
// ---------------------------------------------------------------------------
__global__ __launch_bounds__(256, 2)
void sgemm_bias_kernel(const float* __restrict__ A,
                       const float* __restrict__ B,
                       const float* __restrict__ bias,
                       float* __restrict__ C,
                       int M, int N, int K)
{
    constexpr int BM = 128, BN = 128, BK = 8, TM = 8, TN = 8;
    __shared__ float As[BK][BM];
    __shared__ float Bs[BK][BN];

    const int tid  = threadIdx.x;
    const int brow = blockIdx.y;
    const int bcol = blockIdx.x;

    const float* Ab = A + (size_t)brow * BM * K;
    const float* Bb = B + (size_t)bcol * BN;

    const int tx = tid % (BN / TN);   // 0..15
    const int ty = tid / (BN / TN);   // 0..15

    // Load mapping
    const int arow  = tid / 2;            // 0..127
    const int acol  = (tid % 2) * 4;      // 0 or 4
    const int bkrow = tid / 32;           // 0..7
    const int bncol = (tid % 32) * 4;     // 0..124

    float acc[TM][TN];
    #pragma unroll
    for (int i = 0; i < TM; i++)
        #pragma unroll
        for (int j = 0; j < TN; j++) acc[i][j] = 0.0f;

    for (int k0 = 0; k0 < K; k0 += BK) {
        float4 a4 = *(const float4*)(Ab + (size_t)arow * K + k0 + acol);
        As[acol + 0][arow] = a4.x;
        As[acol + 1][arow] = a4.y;
        As[acol + 2][arow] = a4.z;
        As[acol + 3][arow] = a4.w;
        float4 b4 = *(const float4*)(Bb + (size_t)(k0 + bkrow) * N + bncol);
        *(float4*)&Bs[bkrow][bncol] = b4;
        __syncthreads();

        #pragma unroll
        for (int k = 0; k < BK; k++) {
            float ar[TM], br[TN];
            #pragma unroll
            for (int i = 0; i < TM; i += 4)
                *(float4*)&ar[i] = *(const float4*)&As[k][ty * TM + i];
            #pragma unroll
            for (int j = 0; j < TN; j += 4)
                *(float4*)&br[j] = *(const float4*)&Bs[k][tx * TN + j];
            #pragma unroll
            for (int i = 0; i < TM; i++)
                #pragma unroll
                for (int j = 0; j < TN; j++)
                    acc[i][j] += ar[i] * br[j];
        }
        __syncthreads();
    }

    // Store with bias
    #pragma unroll
    for (int i = 0; i < TM; i++) {
        const int row = brow * BM + ty * TM + i;
        float* crow = C + (size_t)row * N + bcol * BN + tx * TN;
        const float* bp = bias + bcol * BN + tx * TN;
        #pragma unroll
        for (int j = 0; j < TN; j += 4) {
            float4 r;
            r.x = acc[i][j + 0] + bp[j + 0];
            r.y = acc[i][j + 1] + bp[j + 1];
            r.z = acc[i][j + 2] + bp[j + 2];
            r.w = acc[i][j + 3] + bp[j + 3];
            *(float4*)(crow + j) = r;
        }
    }
}

// ---------------------------------------------------------------------------
// Causal flash attention, fp32. One thread per query row, 128 rows per block.
// qkv layout: [B, T, 3C] with q at [h*64], k at [C + h*64], v at [2C + h*64].
// Output: [B, T, C] (head-major interleave matching reference transpose-back).
// ---------------------------------------------------------------------------
#define BQ 128
#define BKV 32

__global__ __launch_bounds__(BQ, 2)
void attn_kernel(const float* __restrict__ qkv, float* __restrict__ out)
{
    const int qb = blockIdx.x;       // query tile
    const int h  = blockIdx.y;       // head
    const int b  = blockIdx.z;       // batch
    const int tid = threadIdx.x;
    const int qi  = qb * BQ + tid;   // global query index (always < TT)

    __shared__ float sK[BKV][DD];
    __shared__ float sV[BKV][DD];

    const float scale = 0.125f;      // 1/sqrt(64)

    // Load q row into registers (pre-scaled)
    const float* qptr = qkv + ((size_t)(b * TT + qi)) * (3 * CC) + h * DD;
    float q[DD];
    #pragma unroll
    for (int d = 0; d < DD; d += 4) {
        float4 v = *(const float4*)(qptr + d);
        q[d + 0] = v.x * scale;
        q[d + 1] = v.y * scale;
        q[d + 2] = v.z * scale;
        q[d + 3] = v.w * scale;
    }

    float acc[DD];
    #pragma unroll
    for (int d = 0; d < DD; d++) acc[d] = 0.0f;
    float m = -1e30f, l = 0.0f;

    const int kend = qb * BQ + BQ;   // causal bound for this block (exclusive)

    for (int k0 = 0; k0 < kend; k0 += BKV) {
        // Cooperative K/V tile load: 32 rows x 16 float4
        #pragma unroll
        for (int i = tid; i < BKV * (DD / 4); i += BQ) {
            const int j  = i / (DD / 4);
            const int d4 = (i % (DD / 4)) * 4;
            const float* kp = qkv + ((size_t)(b * TT + k0 + j)) * (3 * CC)
                              + CC + h * DD + d4;
            *(float4*)&sK[j][d4] = *(const float4*)kp;
            *(float4*)&sV[j][d4] = *(const float4*)(kp + CC);
        }
        __syncthreads();

        // Scores
        float s[BKV];
        #pragma unroll 4
        for (int j = 0; j < BKV; j++) {
            float s0 = 0.f, s1 = 0.f, s2 = 0.f, s3 = 0.f;
            #pragma unroll
            for (int d = 0; d < DD; d += 4) {
                float4 kv = *(const float4*)&sK[j][d];
                s0 += q[d + 0] * kv.x;
                s1 += q[d + 1] * kv.y;
                s2 += q[d + 2] * kv.z;
                s3 += q[d + 3] * kv.w;
            }
            s[j] = (s0 + s1) + (s2 + s3);
        }

        // Causal mask + running max
        float mt = m;
        #pragma unroll
        for (int j = 0; j < BKV; j++) {
            if (k0 + j > qi) s[j] = -1e30f;
            mt = fmaxf(mt, s[j]);
        }

        const float corr = __expf(m - mt);
        l *= corr;
        #pragma unroll
        for (int d = 0; d < DD; d++) acc[d] *= corr;

        #pragma unroll 4
        for (int j = 0; j < BKV; j++) {
            const float p = __expf(s[j] - mt);
            l += p;
            #pragma unroll
            for (int d = 0; d < DD; d += 4) {
                float4 vv = *(const float4*)&sV[j][d];
                acc[d + 0] += p * vv.x;
                acc[d + 1] += p * vv.y;
                acc[d + 2] += p * vv.z;
                acc[d + 3] += p * vv.w;
            }
        }
        m = mt;
        __syncthreads();
    }

    const float inv = 1.0f / l;
    float* op = out + ((size_t)(b * TT + qi)) * CC + h * DD;
    #pragma unroll
    for (int d = 0; d < DD; d += 4) {
        float4 r;
        r.x = acc[d + 0] * inv;
        r.y = acc[d + 1] * inv;
        r.z = acc[d + 2] * inv;
        r.w = acc[d + 3] * inv;
        *(float4*)(op + d) = r;
    }
}

// ---------------------------------------------------------------------------
// Launch
// ---------------------------------------------------------------------------
extern "C" void kernel_launch(void* const* d_in, const int* in_sizes, int n_in,
                              void* d_out, int out_size)
{
    const float* x     = (const float*)d_in[0];
    const float* w_qkv = (const float*)d_in[1];
    const float* b_qkv = (const float*)d_in[2];
    const float* w_out = (const float*)d_in[3];
    const float* b_out = (const float*)d_in[4];
    float* out = (float*)d_out;

    float* qkv = nullptr;
    float* att = nullptr;
    cudaGetSymbolAddress((void**)&qkv, g_qkv);
    cudaGetSymbolAddress((void**)&att, g_att);

    // QKV projection: [8192,1024] @ [1024,3072] + b
    {
        dim3 grid((3 * CC) / 128, MM / 128);
        sgemm_bias_kernel<<<grid, 256>>>(x, w_qkv, b_qkv, qkv, MM, 3 * CC, CC);
    }

    // Causal flash attention
    {
        dim3 grid(TT / BQ, HH, BB);
        attn_kernel<<<grid, BQ>>>(qkv, att);
    }

    // Output projection: [8192,1024] @ [1024,1024] + b
    {
        dim3 grid(CC / 128, MM / 128);
        sgemm_bias_kernel<<<grid, 256>>>(att, w_out, b_out, out, MM, CC, CC);
    }
}

// round 3
// speedup vs baseline: 1.5453x; 1.5453x over previous
#include <cuda_runtime.h>
#include <cuda_bf16.h>
#include <cstdint>

// Problem constants
#define BB 4
#define TT 2048
#define CC 1024
#define HH 16
#define DD 64
#define MM (BB*TT)        // 8192

// Scratch (device globals: allocation-free rule)
__device__ float g_qkv[(size_t)MM * 3 * CC];     // [8192, 3072]
__device__ float g_att[(size_t)MM * CC];         // [8192, 1024] (tf32-rounded)
__device__ float g_x32[(size_t)MM * CC];         // tf32-rounded x
__device__ float g_wqkvT[(size_t)3 * CC * CC];   // [3072, 1024] (w_qkv^T, tf32)
__device__ float g_woutT[(size_t)CC * CC];       // [1024, 1024] (w_out^T, tf32)

// ---------------------------------------------------------------------------
// Helpers
// ---------------------------------------------------------------------------
__device__ __forceinline__ uint32_t smem_u32(const void* p) {
    uint32_t a;
    asm("{ .reg .u64 t; cvta.to.shared.u64 t, %1; cvt.u32.u64 %0, t; }"
        : "=r"(a) : "l"(p));
    return a;
}

__device__ __forceinline__ float to_tf32(float x) {
    uint32_t u;
    asm("cvt.rna.tf32.f32 %0, %1;" : "=r"(u) : "f"(x));
    return __uint_as_float(u);
}

__device__ __forceinline__ void cp_async16(uint32_t dst, const void* src) {
    asm volatile("cp.async.cg.shared.global [%0], [%1], 16;\n"
                 :: "r"(dst), "l"(src));
}
__device__ __forceinline__ void cp_commit() {
    asm volatile("cp.async.commit_group;\n" ::: "memory");
}
__device__ __forceinline__ void cp_wait1() {
    asm volatile("cp.async.wait_group 1;\n" ::: "memory");
}
__device__ __forceinline__ void cp_wait0() {
    asm volatile("cp.async.wait_group 0;\n" ::: "memory");
}

// m16n8k8 tf32 mma, fp32 accumulate
__device__ __forceinline__ void mma_tf32(float* c, const float* a, const float* b) {
    asm volatile(
        "mma.sync.aligned.m16n8k8.row.col.f32.tf32.tf32.f32 "
        "{%0,%1,%2,%3}, {%4,%5,%6,%7}, {%8,%9}, {%0,%1,%2,%3};\n"
        : "+f"(c[0]), "+f"(c[1]), "+f"(c[2]), "+f"(c[3])
        : "r"(__float_as_uint(a[0])), "r"(__float_as_uint(a[1])),
          "r"(__float_as_uint(a[2])), "r"(__float_as_uint(a[3])),
          "r"(__float_as_uint(b[0])), "r"(__float_as_uint(b[1])));
}

// ---------------------------------------------------------------------------
// Elementwise tf32 round: y = tf32(x)
// ---------------------------------------------------------------------------
__global__ void tf32_convert_kernel(const float* __restrict__ in,
                                    float* __restrict__ out, int n)
{
    int i = (blockIdx.x * blockDim.x + threadIdx.x) * 4;
    if (i < n) {
        float4 v = *(const float4*)(in + i);
        v.x = to_tf32(v.x); v.y = to_tf32(v.y);
        v.z = to_tf32(v.z); v.w = to_tf32(v.w);
        *(float4*)(out + i) = v;
    }
}

// ---------------------------------------------------------------------------
// Weight transpose with tf32 rounding: out[c][r] = tf32(in[r][c])
// ---------------------------------------------------------------------------
__global__ void transpose_kernel(const float* __restrict__ in,
                                 float* __restrict__ out, int R, int C_)
{
    __shared__ float tile[32][33];
    const int c0 = blockIdx.x * 32, r0 = blockIdx.y * 32;
    const int tx = threadIdx.x, ty = threadIdx.y;   // 32 x 8
    #pragma unroll
    for (int i = 0; i < 32; i += 8)
        tile[ty + i][tx] = in[(size_t)(r0 + ty + i) * C_ + c0 + tx];
    __syncthreads();
    #pragma unroll
    for (int i = 0; i < 32; i += 8)
        out[(size_t)(c0 + ty + i) * R + r0 + tx] = to_tf32(tile[tx][ty + i]);
}

// ---------------------------------------------------------------------------
// tf32 mma.sync GEMM: C[M,N] = A[M,K] @ Bt[N,K]^T + bias[N]
// 128x128 CTA tile, BK=16, 256 threads (8 warps, 2x4), warp tile 64x32.
// 2-stage cp.async pipeline. A, Bt must be pre-rounded to tf32.
// ---------------------------------------------------------------------------
#define GBM 128
#define GBN 128
#define GBK 16
#define SPAD 20   // floats per smem row (16 + 4 pad): conflict-free frag loads

__global__ __launch_bounds__(256, 2)
void gemm_tf32_kernel(const float* __restrict__ A, const float* __restrict__ Bt,
                      const float* __restrict__ bias, float* __restrict__ C,
                      int M, int N, int K)
{
    __shared__ __align__(16) float As[2][GBM][SPAD];
    __shared__ __align__(16) float Bs[2][GBN][SPAD];

    const int tid  = threadIdx.x;
    const int wid  = tid >> 5;
    const int lane = tid & 31;
    const int gid  = lane >> 2;       // group id 0..7
    const int tig  = lane & 3;        // thread-in-group 0..3

    const int warp_m = wid & 1;       // 0..1  (64 rows each)
    const int warp_n = wid >> 1;      // 0..3  (32 cols each)

    const int brow = blockIdx.y, bcol = blockIdx.x;
    const float* Abase = A  + (size_t)brow * GBM * K;
    const float* Bbase = Bt + (size_t)bcol * GBN * K;

    // Per-thread load slots: 2 x 16B for A, 2 x 16B for B per tile
    const int lrow0 = tid >> 1;                 // 0..127 (idx = tid)
    const int lc0   = (tid & 1) * 4;            // wait—recompute below
    (void)lrow0; (void)lc0;

    float acc[4][4][4];
    #pragma unroll
    for (int i = 0; i < 4; i++)
        #pragma unroll
        for (int j = 0; j < 4; j++)
            #pragma unroll
            for (int r = 0; r < 4; r++) acc[i][j][r] = 0.0f;

    const uint32_t sA0 = smem_u32(&As[0][0][0]);
    const uint32_t sB0 = smem_u32(&Bs[0][0][0]);
    const uint32_t stageBytes = GBM * SPAD * 4;

    // tile loader: 512 float4 per matrix, 256 threads -> 2 each
    auto load_tile = [&](int it, int stage) {
        const int koff = it * GBK;
        #pragma unroll
        for (int q = 0; q < 2; q++) {
            const int idx = q * 256 + tid;        // 0..511
            const int row = idx >> 2;             // 0..127
            const int c4  = (idx & 3) * 4;        // 0,4,8,12
            const uint32_t doff = stage * stageBytes + (row * SPAD + c4) * 4;
            cp_async16(sA0 + doff, Abase + (size_t)row * K + koff + c4);
            cp_async16(sB0 + doff, Bbase + (size_t)row * K + koff + c4);
        }
    };

    const int nit = K / GBK;
    load_tile(0, 0);
    cp_commit();

    for (int it = 0; it < nit; ++it) {
        if (it + 1 < nit) {
            load_tile(it + 1, (it + 1) & 1);
            cp_commit();
            cp_wait1();
        } else {
            cp_wait0();
        }
        __syncthreads();

        const int st = it & 1;
        #pragma unroll
        for (int kk = 0; kk < GBK; kk += 8) {
            float a[4][4], b[4][2];
            #pragma unroll
            for (int i = 0; i < 4; i++) {
                const int r = warp_m * 64 + i * 16 + gid;
                a[i][0] = As[st][r][kk + tig];
                a[i][1] = As[st][r + 8][kk + tig];
                a[i][2] = As[st][r][kk + tig + 4];
                a[i][3] = As[st][r + 8][kk + tig + 4];
            }
            #pragma unroll
            for (int j = 0; j < 4; j++) {
                const int r = warp_n * 32 + j * 8 + gid;
                b[j][0] = Bs[st][r][kk + tig];
                b[j][1] = Bs[st][r][kk + tig + 4];
            }
            #pragma unroll
            for (int i = 0; i < 4; i++)
                #pragma unroll
                for (int j = 0; j < 4; j++)
                    mma_tf32(acc[i][j], a[i], b[j]);
        }
        __syncthreads();
    }

    // Epilogue: each (i,j) tile: rows gid, gid+8; cols 2*tig, 2*tig+1
    #pragma unroll
    for (int i = 0; i < 4; i++) {
        const int row0 = brow * GBM + warp_m * 64 + i * 16 + gid;
        #pragma unroll
        for (int j = 0; j < 4; j++) {
            const int col = bcol * GBN + warp_n * 32 + j * 8 + 2 * tig;
            const float bx = bias[col], by = bias[col + 1];
            float2 v0 = make_float2(acc[i][j][0] + bx, acc[i][j][1] + by);
            float2 v1 = make_float2(acc[i][j][2] + bx, acc[i][j][3] + by);
            *(float2*)(C + (size_t)row0 * N + col) = v0;
            *(float2*)(C + (size_t)(row0 + 8) * N + col) = v1;
        }
    }
}

// ---------------------------------------------------------------------------
// Causal flash attention, fp32. One thread per query row.
// Output rounded to tf32 (feeds the out-proj mma GEMM).
// ---------------------------------------------------------------------------
#define BQ 128
#define BKV 32

__global__ __launch_bounds__(BQ, 2)
void attn_kernel(const float* __restrict__ qkv, float* __restrict__ out)
{
    const int qb = blockIdx.x;
    const int h  = blockIdx.y;
    const int b  = blockIdx.z;
    const int tid = threadIdx.x;
    const int qi  = qb * BQ + tid;

    __shared__ float sK[BKV][DD];
    __shared__ float sV[BKV][DD];

    const float scale = 0.125f;

    const float* qptr = qkv + ((size_t)(b * TT + qi)) * (3 * CC) + h * DD;
    float q[DD];
    #pragma unroll
    for (int d = 0; d < DD; d += 4) {
        float4 v = *(const float4*)(qptr + d);
        q[d + 0] = v.x * scale;
        q[d + 1] = v.y * scale;
        q[d + 2] = v.z * scale;
        q[d + 3] = v.w * scale;
    }

    float acc[DD];
    #pragma unroll
    for (int d = 0; d < DD; d++) acc[d] = 0.0f;
    float m = -1e30f, l = 0.0f;

    const int kend = qb * BQ + BQ;

    for (int k0 = 0; k0 < kend; k0 += BKV) {
        #pragma unroll
        for (int i = tid; i < BKV * (DD / 4); i += BQ) {
            const int j  = i / (DD / 4);
            const int d4 = (i % (DD / 4)) * 4;
            const float* kp = qkv + ((size_t)(b * TT + k0 + j)) * (3 * CC)
                              + CC + h * DD + d4;
            *(float4*)&sK[j][d4] = *(const float4*)kp;
            *(float4*)&sV[j][d4] = *(const float4*)(kp + CC);
        }
        __syncthreads();

        float s[BKV];
        #pragma unroll 4
        for (int j = 0; j < BKV; j++) {
            float s0 = 0.f, s1 = 0.f, s2 = 0.f, s3 = 0.f;
            #pragma unroll
            for (int d = 0; d < DD; d += 4) {
                float4 kv = *(const float4*)&sK[j][d];
                s0 += q[d + 0] * kv.x;
                s1 += q[d + 1] * kv.y;
                s2 += q[d + 2] * kv.z;
                s3 += q[d + 3] * kv.w;
            }
            s[j] = (s0 + s1) + (s2 + s3);
        }

        float mt = m;
        #pragma unroll
        for (int j = 0; j < BKV; j++) {
            if (k0 + j > qi) s[j] = -1e30f;
            mt = fmaxf(mt, s[j]);
        }

        const float corr = __expf(m - mt);
        l *= corr;
        #pragma unroll
        for (int d = 0; d < DD; d++) acc[d] *= corr;

        #pragma unroll 4
        for (int j = 0; j < BKV; j++) {
            const float p = __expf(s[j] - mt);
            l += p;
            #pragma unroll
            for (int d = 0; d < DD; d += 4) {
                float4 vv = *(const float4*)&sV[j][d];
                acc[d + 0] += p * vv.x;
                acc[d + 1] += p * vv.y;
                acc[d + 2] += p * vv.z;
                acc[d + 3] += p * vv.w;
            }
        }
        m = mt;
        __syncthreads();
    }

    const float inv = 1.0f / l;
    float* op = out + ((size_t)(b * TT + qi)) * CC + h * DD;
    #pragma unroll
    for (int d = 0; d < DD; d += 4) {
        float4 r;
        r.x = to_tf32(acc[d + 0] * inv);
        r.y = to_tf32(acc[d + 1] * inv);
        r.z = to_tf32(acc[d + 2] * inv);
        r.w = to_tf32(acc[d + 3] * inv);
        *(float4*)(op + d) = r;
    }
}

// ---------------------------------------------------------------------------
// Launch
// ---------------------------------------------------------------------------
extern "C" void kernel_launch(void* const* d_in, const int* in_sizes, int n_in,
                              void* d_out, int out_size)
{
    const float* x     = (const float*)d_in[0];
    const float* w_qkv = (const float*)d_in[1];
    const float* b_qkv = (const float*)d_in[2];
    const float* w_out = (const float*)d_in[3];
    const float* b_out = (const float*)d_in[4];
    float* out = (float*)d_out;

    float* qkv = nullptr;   cudaGetSymbolAddress((void**)&qkv, g_qkv);
    float* att = nullptr;   cudaGetSymbolAddress((void**)&att, g_att);
    float* x32 = nullptr;   cudaGetSymbolAddress((void**)&x32, g_x32);
    float* wqkvT = nullptr; cudaGetSymbolAddress((void**)&wqkvT, g_wqkvT);
    float* woutT = nullptr; cudaGetSymbolAddress((void**)&woutT, g_woutT);

    // Pre-round x to tf32; transpose+round weights to [N,K]
    {
        const int n = MM * CC;
        tf32_convert_kernel<<<n / (256 * 4), 256>>>(x, x32, n);
        dim3 blk(32, 8);
        transpose_kernel<<<dim3((3 * CC) / 32, CC / 32), blk>>>(w_qkv, wqkvT, CC, 3 * CC);
        transpose_kernel<<<dim3(CC / 32, CC / 32), blk>>>(w_out, woutT, CC, CC);
    }

    // QKV projection (tf32 mma.sync)
    {
        dim3 grid((3 * CC) / GBN, MM / GBM);
        gemm_tf32_kernel<<<grid, 256>>>(x32, wqkvT, b_qkv, qkv, MM, 3 * CC, CC);
    }

    // Causal flash attention (fp32)
    {
        dim3 grid(TT / BQ, HH, BB);
        attn_kernel<<<grid, BQ>>>(qkv, att);
    }

    // Output projection (tf32 mma.sync)
    {
        dim3 grid(CC / GBN, MM / GBM);
        gemm_tf32_kernel<<<grid, 256>>>(att, woutT, b_out, out, MM, CC, CC);
    }
}

// round 4
// speedup vs baseline: 3.0006x; 1.9417x over previous
#include <cuda_runtime.h>
#include <cuda_bf16.h>
#include <cstdint>

// Problem constants
#define BB 4
#define TT 2048
#define CC 1024
#define HH 16
#define DD 64
#define MM (BB*TT)        // 8192

// Scratch (device globals: allocation-free rule)
__device__ float g_qkv[(size_t)MM * 3 * CC];     // [8192, 3072]
__device__ float g_att[(size_t)MM * CC];         // [8192, 1024] (tf32-rounded)
__device__ float g_x32[(size_t)MM * CC];         // tf32-rounded x
__device__ float g_wqkvT[(size_t)3 * CC * CC];   // [3072, 1024] (w_qkv^T, tf32)
__device__ float g_woutT[(size_t)CC * CC];       // [1024, 1024] (w_out^T, tf32)

// ---------------------------------------------------------------------------
// Helpers
// ---------------------------------------------------------------------------
__device__ __forceinline__ uint32_t smem_u32(const void* p) {
    uint32_t a;
    asm("{ .reg .u64 t; cvta.to.shared.u64 t, %1; cvt.u32.u64 %0, t; }"
        : "=r"(a) : "l"(p));
    return a;
}

__device__ __forceinline__ float to_tf32(float x) {
    uint32_t u;
    asm("cvt.rna.tf32.f32 %0, %1;" : "=r"(u) : "f"(x));
    return __uint_as_float(u);
}

__device__ __forceinline__ float ex2(float x) {
    float y;
    asm("ex2.approx.ftz.f32 %0, %1;" : "=f"(y) : "f"(x));
    return y;
}

__device__ __forceinline__ void cp_async16(uint32_t dst, const void* src) {
    asm volatile("cp.async.cg.shared.global [%0], [%1], 16;\n"
                 :: "r"(dst), "l"(src));
}
__device__ __forceinline__ void cp_commit() {
    asm volatile("cp.async.commit_group;\n" ::: "memory");
}
__device__ __forceinline__ void cp_wait1() {
    asm volatile("cp.async.wait_group 1;\n" ::: "memory");
}
__device__ __forceinline__ void cp_wait0() {
    asm volatile("cp.async.wait_group 0;\n" ::: "memory");
}

// m16n8k8 tf32 mma, fp32 accumulate
__device__ __forceinline__ void mma_tf32(float* c, const float* a, const float* b) {
    asm volatile(
        "mma.sync.aligned.m16n8k8.row.col.f32.tf32.tf32.f32 "
        "{%0,%1,%2,%3}, {%4,%5,%6,%7}, {%8,%9}, {%0,%1,%2,%3};\n"
        : "+f"(c[0]), "+f"(c[1]), "+f"(c[2]), "+f"(c[3])
        : "r"(__float_as_uint(a[0])), "r"(__float_as_uint(a[1])),
          "r"(__float_as_uint(a[2])), "r"(__float_as_uint(a[3])),
          "r"(__float_as_uint(b[0])), "r"(__float_as_uint(b[1])));
}

__device__ __forceinline__ void mma_tf32b(float* c, const float* a,
                                          float b0, float b1) {
    asm volatile(
        "mma.sync.aligned.m16n8k8.row.col.f32.tf32.tf32.f32 "
        "{%0,%1,%2,%3}, {%4,%5,%6,%7}, {%8,%9}, {%0,%1,%2,%3};\n"
        : "+f"(c[0]), "+f"(c[1]), "+f"(c[2]), "+f"(c[3])
        : "r"(__float_as_uint(a[0])), "r"(__float_as_uint(a[1])),
          "r"(__float_as_uint(a[2])), "r"(__float_as_uint(a[3])),
          "r"(__float_as_uint(b0)), "r"(__float_as_uint(b1)));
}

// ---------------------------------------------------------------------------
// Elementwise tf32 round
// ---------------------------------------------------------------------------
__global__ void tf32_convert_kernel(const float* __restrict__ in,
                                    float* __restrict__ out, int n)
{
    int i = (blockIdx.x * blockDim.x + threadIdx.x) * 4;
    if (i < n) {
        float4 v = *(const float4*)(in + i);
        v.x = to_tf32(v.x); v.y = to_tf32(v.y);
        v.z = to_tf32(v.z); v.w = to_tf32(v.w);
        *(float4*)(out + i) = v;
    }
}

// ---------------------------------------------------------------------------
// Weight transpose with tf32 rounding
// ---------------------------------------------------------------------------
__global__ void transpose_kernel(const float* __restrict__ in,
                                 float* __restrict__ out, int R, int C_)
{
    __shared__ float tile[32][33];
    const int c0 = blockIdx.x * 32, r0 = blockIdx.y * 32;
    const int tx = threadIdx.x, ty = threadIdx.y;   // 32 x 8
    #pragma unroll
    for (int i = 0; i < 32; i += 8)
        tile[ty + i][tx] = in[(size_t)(r0 + ty + i) * C_ + c0 + tx];
    __syncthreads();
    #pragma unroll
    for (int i = 0; i < 32; i += 8)
        out[(size_t)(c0 + ty + i) * R + r0 + tx] = to_tf32(tile[tx][ty + i]);
}

// ---------------------------------------------------------------------------
// tf32 mma.sync GEMM (unchanged, passing): C = A @ Bt^T + bias
// ---------------------------------------------------------------------------
#define GBM 128
#define GBN 128
#define GBK 16
#define SPAD 20

__global__ __launch_bounds__(256, 2)
void gemm_tf32_kernel(const float* __restrict__ A, const float* __restrict__ Bt,
                      const float* __restrict__ bias, float* __restrict__ C,
                      int M, int N, int K)
{
    __shared__ __align__(16) float As[2][GBM][SPAD];
    __shared__ __align__(16) float Bs[2][GBN][SPAD];

    const int tid  = threadIdx.x;
    const int wid  = tid >> 5;
    const int lane = tid & 31;
    const int gid  = lane >> 2;
    const int tig  = lane & 3;

    const int warp_m = wid & 1;
    const int warp_n = wid >> 1;

    const int brow = blockIdx.y, bcol = blockIdx.x;
    const float* Abase = A  + (size_t)brow * GBM * K;
    const float* Bbase = Bt + (size_t)bcol * GBN * K;

    float acc[4][4][4];
    #pragma unroll
    for (int i = 0; i < 4; i++)
        #pragma unroll
        for (int j = 0; j < 4; j++)
            #pragma unroll
            for (int r = 0; r < 4; r++) acc[i][j][r] = 0.0f;

    const uint32_t sA0 = smem_u32(&As[0][0][0]);
    const uint32_t sB0 = smem_u32(&Bs[0][0][0]);
    const uint32_t stageBytes = GBM * SPAD * 4;

    auto load_tile = [&](int it, int stage) {
        const int koff = it * GBK;
        #pragma unroll
        for (int q = 0; q < 2; q++) {
            const int idx = q * 256 + tid;
            const int row = idx >> 2;
            const int c4  = (idx & 3) * 4;
            const uint32_t doff = stage * stageBytes + (row * SPAD + c4) * 4;
            cp_async16(sA0 + doff, Abase + (size_t)row * K + koff + c4);
            cp_async16(sB0 + doff, Bbase + (size_t)row * K + koff + c4);
        }
    };

    const int nit = K / GBK;
    load_tile(0, 0);
    cp_commit();

    for (int it = 0; it < nit; ++it) {
        if (it + 1 < nit) {
            load_tile(it + 1, (it + 1) & 1);
            cp_commit();
            cp_wait1();
        } else {
            cp_wait0();
        }
        __syncthreads();

        const int st = it & 1;
        #pragma unroll
        for (int kk = 0; kk < GBK; kk += 8) {
            float a[4][4], b[4][2];
            #pragma unroll
            for (int i = 0; i < 4; i++) {
                const int r = warp_m * 64 + i * 16 + gid;
                a[i][0] = As[st][r][kk + tig];
                a[i][1] = As[st][r + 8][kk + tig];
                a[i][2] = As[st][r][kk + tig + 4];
                a[i][3] = As[st][r + 8][kk + tig + 4];
            }
            #pragma unroll
            for (int j = 0; j < 4; j++) {
                const int r = warp_n * 32 + j * 8 + gid;
                b[j][0] = Bs[st][r][kk + tig];
                b[j][1] = Bs[st][r][kk + tig + 4];
            }
            #pragma unroll
            for (int i = 0; i < 4; i++)
                #pragma unroll
                for (int j = 0; j < 4; j++)
                    mma_tf32(acc[i][j], a[i], b[j]);
        }
        __syncthreads();
    }

    #pragma unroll
    for (int i = 0; i < 4; i++) {
        const int row0 = brow * GBM + warp_m * 64 + i * 16 + gid;
        #pragma unroll
        for (int j = 0; j < 4; j++) {
            const int col = bcol * GBN + warp_n * 32 + j * 8 + 2 * tig;
            const float bx = bias[col], by = bias[col + 1];
            float2 v0 = make_float2(acc[i][j][0] + bx, acc[i][j][1] + by);
            float2 v1 = make_float2(acc[i][j][2] + bx, acc[i][j][3] + by);
            *(float2*)(C + (size_t)row0 * N + col) = v0;
            *(float2*)(C + (size_t)(row0 + 8) * N + col) = v1;
        }
    }
}

// ---------------------------------------------------------------------------
// Flash attention with tf32 mma.sync.
// CTA: 128 q rows x one (b,h); 8 warps x 16 rows; kv tiles of 64.
// S = Q (tf32, exp2-domain prescaled) @ [Khi + Klo]^T  (K error-compensated)
// P -> smem (tf32), O += P @ V (V transposed in smem, tf32).
// ---------------------------------------------------------------------------
#define APAD 68   // smem row pitch (floats); 68 % 32 == 4 -> conflict-free frags

__global__ __launch_bounds__(256, 2)
void attn_mma_kernel(const float* __restrict__ qkv, float* __restrict__ out)
{
    extern __shared__ __align__(16) float dsm[];
    constexpr int OFF_P  = 0;                 // 128 x 68
    constexpr int OFF_KH = 128 * APAD;        // 64 x 68
    constexpr int OFF_KL = OFF_KH + 64 * APAD;
    constexpr int OFF_VT = OFF_KL + 64 * APAD;

    const int qb = (int)gridDim.x - 1 - (int)blockIdx.x;  // heavy tiles first
    const int h  = blockIdx.y;
    const int b  = blockIdx.z;
    const int q0 = qb * 128;

    const int tid  = threadIdx.x;
    const int w    = tid >> 5;
    const int lane = tid & 31;
    const int gid  = lane >> 2;
    const int tig  = lane & 3;

    // Stage Q: scaled into exp2 domain, tf32-rounded
    const float SC = 0.125f * 1.4426950408889634f;
    {
        const float* qb_ptr = qkv + ((size_t)(b * TT + q0)) * (3 * CC) + h * DD;
        for (int idx = tid; idx < 128 * 16; idx += 256) {
            const int row = idx >> 4, c4 = (idx & 15) << 2;
            float4 v = *(const float4*)(qb_ptr + (size_t)row * (3 * CC) + c4);
            float* d = &dsm[OFF_P + row * APAD + c4];
            d[0] = to_tf32(v.x * SC);
            d[1] = to_tf32(v.y * SC);
            d[2] = to_tf32(v.z * SC);
            d[3] = to_tf32(v.w * SC);
        }
    }
    __syncthreads();

    const int r0l = w * 16 + gid;      // local q row (c0/c1)
    const int r0g = q0 + r0l;          // global q row

    float qf[8][4];
    #pragma unroll
    for (int ks = 0; ks < 8; ks++) {
        const int kb = ks * 8 + tig;
        qf[ks][0] = dsm[OFF_P + r0l * APAD + kb];
        qf[ks][1] = dsm[OFF_P + (r0l + 8) * APAD + kb];
        qf[ks][2] = dsm[OFF_P + r0l * APAD + kb + 4];
        qf[ks][3] = dsm[OFF_P + (r0l + 8) * APAD + kb + 4];
    }

    float O[8][4];
    #pragma unroll
    for (int j = 0; j < 8; j++)
        #pragma unroll
        for (int r = 0; r < 4; r++) O[j][r] = 0.0f;
    float m0 = -1e30f, m1 = -1e30f, l0 = 0.0f, l1 = 0.0f;

    const int ntiles = 2 * (qb + 1);

    for (int t = 0; t < ntiles; t++) {
        const int kv0 = t * 64;

        // Load K tile (hi/lo split) and V tile (transposed), tf32-rounded
        for (int idx = tid; idx < 64 * 16; idx += 256) {
            const int row = idx >> 4, c4 = (idx & 15) << 2;
            const float* kp = qkv + ((size_t)(b * TT + kv0 + row)) * (3 * CC)
                              + CC + h * DD + c4;
            float4 k4 = *(const float4*)kp;
            float4 v4 = *(const float4*)(kp + CC);
            float* kh = &dsm[OFF_KH + row * APAD + c4];
            float* kl = &dsm[OFF_KL + row * APAD + c4];
            float hx = to_tf32(k4.x); kh[0] = hx; kl[0] = to_tf32(k4.x - hx);
            float hy = to_tf32(k4.y); kh[1] = hy; kl[1] = to_tf32(k4.y - hy);
            float hz = to_tf32(k4.z); kh[2] = hz; kl[2] = to_tf32(k4.z - hz);
            float hw = to_tf32(k4.w); kh[3] = hw; kl[3] = to_tf32(k4.w - hw);
            dsm[OFF_VT + (c4 + 0) * APAD + row] = to_tf32(v4.x);
            dsm[OFF_VT + (c4 + 1) * APAD + row] = to_tf32(v4.y);
            dsm[OFF_VT + (c4 + 2) * APAD + row] = to_tf32(v4.z);
            dsm[OFF_VT + (c4 + 3) * APAD + row] = to_tf32(v4.w);
        }
        __syncthreads();

        // S = Q @ K^T  (hi + lo)
        float s[8][4];
        #pragma unroll
        for (int j = 0; j < 8; j++)
            #pragma unroll
            for (int r = 0; r < 4; r++) s[j][r] = 0.0f;

        #pragma unroll
        for (int ks = 0; ks < 8; ks++) {
            const int kb = ks * 8 + tig;
            #pragma unroll
            for (int j = 0; j < 8; j++) {
                const int rb = (j * 8 + gid) * APAD + kb;
                mma_tf32b(s[j], qf[ks], dsm[OFF_KH + rb], dsm[OFF_KH + rb + 4]);
                mma_tf32b(s[j], qf[ks], dsm[OFF_KL + rb], dsm[OFF_KL + rb + 4]);
            }
        }

        // Causal mask on the two diagonal-straddling tiles
        if (t + 2 >= ntiles) {
            #pragma unroll
            for (int j = 0; j < 8; j++) {
                const int col = kv0 + j * 8 + 2 * tig;
                if (col     > r0g)     s[j][0] = -1e30f;
                if (col + 1 > r0g)     s[j][1] = -1e30f;
                if (col     > r0g + 8) s[j][2] = -1e30f;
                if (col + 1 > r0g + 8) s[j][3] = -1e30f;
            }
        }

        // Online softmax (exp2 domain)
        float mt0 = s[0][0], mt1 = s[0][2];
        #pragma unroll
        for (int j = 0; j < 8; j++) {
            mt0 = fmaxf(mt0, fmaxf(s[j][0], s[j][1]));
            mt1 = fmaxf(mt1, fmaxf(s[j][2], s[j][3]));
        }
        mt0 = fmaxf(mt0, __shfl_xor_sync(0xffffffffu, mt0, 1));
        mt0 = fmaxf(mt0, __shfl_xor_sync(0xffffffffu, mt0, 2));
        mt1 = fmaxf(mt1, __shfl_xor_sync(0xffffffffu, mt1, 1));
        mt1 = fmaxf(mt1, __shfl_xor_sync(0xffffffffu, mt1, 2));

        const float mn0 = fmaxf(m0, mt0), mn1 = fmaxf(m1, mt1);
        const float c0 = ex2(m0 - mn0), c1 = ex2(m1 - mn1);
        l0 *= c0; l1 *= c1;
        #pragma unroll
        for (int j = 0; j < 8; j++) {
            O[j][0] *= c0; O[j][1] *= c0;
            O[j][2] *= c1; O[j][3] *= c1;
        }

        #pragma unroll
        for (int j = 0; j < 8; j++) {
            const float p0 = ex2(s[j][0] - mn0), p1 = ex2(s[j][1] - mn0);
            const float p2 = ex2(s[j][2] - mn1), p3 = ex2(s[j][3] - mn1);
            l0 += p0 + p1;
            l1 += p2 + p3;
            const int cb = j * 8 + 2 * tig;
            *(float2*)&dsm[OFF_P + r0l * APAD + cb] =
                make_float2(to_tf32(p0), to_tf32(p1));
            *(float2*)&dsm[OFF_P + (r0l + 8) * APAD + cb] =
                make_float2(to_tf32(p2), to_tf32(p3));
        }
        m0 = mn0; m1 = mn1;
        __syncwarp();

        // O += P @ V
        #pragma unroll
        for (int ks = 0; ks < 8; ks++) {
            const int kb = ks * 8 + tig;
            float a[4];
            a[0] = dsm[OFF_P + r0l * APAD + kb];
            a[1] = dsm[OFF_P + (r0l + 8) * APAD + kb];
            a[2] = dsm[OFF_P + r0l * APAD + kb + 4];
            a[3] = dsm[OFF_P + (r0l + 8) * APAD + kb + 4];
            #pragma unroll
            for (int j = 0; j < 8; j++) {
                const int vb = (j * 8 + gid) * APAD + kb;
                mma_tf32b(O[j], a, dsm[OFF_VT + vb], dsm[OFF_VT + vb + 4]);
            }
        }
        __syncthreads();
    }

    // Finalize: row sums across quad, normalize, store (tf32 for out-proj)
    l0 += __shfl_xor_sync(0xffffffffu, l0, 1);
    l0 += __shfl_xor_sync(0xffffffffu, l0, 2);
    l1 += __shfl_xor_sync(0xffffffffu, l1, 1);
    l1 += __shfl_xor_sync(0xffffffffu, l1, 2);
    const float i0 = 1.0f / l0, i1 = 1.0f / l1;

    float* ob = out + ((size_t)(b * TT + r0g)) * CC + h * DD;
    #pragma unroll
    for (int j = 0; j < 8; j++) {
        const int cb = j * 8 + 2 * tig;
        *(float2*)(ob + cb) =
            make_float2(to_tf32(O[j][0] * i0), to_tf32(O[j][1] * i0));
        *(float2*)(ob + (size_t)8 * CC + cb) =
            make_float2(to_tf32(O[j][2] * i1), to_tf32(O[j][3] * i1));
    }
}

#define ATTN_SMEM ((128 * APAD + 3 * 64 * APAD) * 4)

// ---------------------------------------------------------------------------
// Launch
// ---------------------------------------------------------------------------
extern "C" void kernel_launch(void* const* d_in, const int* in_sizes, int n_in,
                              void* d_out, int out_size)
{
    const float* x     = (const float*)d_in[0];
    const float* w_qkv = (const float*)d_in[1];
    const float* b_qkv = (const float*)d_in[2];
    const float* w_out = (const float*)d_in[3];
    const float* b_out = (const float*)d_in[4];
    float* out = (float*)d_out;

    float* qkv = nullptr;   cudaGetSymbolAddress((void**)&qkv, g_qkv);
    float* att = nullptr;   cudaGetSymbolAddress((void**)&att, g_att);
    float* x32 = nullptr;   cudaGetSymbolAddress((void**)&x32, g_x32);
    float* wqkvT = nullptr; cudaGetSymbolAddress((void**)&wqkvT, g_wqkvT);
    float* woutT = nullptr; cudaGetSymbolAddress((void**)&woutT, g_woutT);

    cudaFuncSetAttribute(attn_mma_kernel,
                         cudaFuncAttributeMaxDynamicSharedMemorySize, ATTN_SMEM);

    // Pre-round x; transpose+round weights
    {
        const int n = MM * CC;
        tf32_convert_kernel<<<n / (256 * 4), 256>>>(x, x32, n);
        dim3 blk(32, 8);
        transpose_kernel<<<dim3((3 * CC) / 32, CC / 32), blk>>>(w_qkv, wqkvT, CC, 3 * CC);
        transpose_kernel<<<dim3(CC / 32, CC / 32), blk>>>(w_out, woutT, CC, CC);
    }

    // QKV projection
    {
        dim3 grid((3 * CC) / GBN, MM / GBM);
        gemm_tf32_kernel<<<grid, 256>>>(x32, wqkvT, b_qkv, qkv, MM, 3 * CC, CC);
    }

    // Flash attention (tf32 mma)
    {
        dim3 grid(TT / 128, HH, BB);
        attn_mma_kernel<<<grid, 256, ATTN_SMEM>>>(qkv, att);
    }

    // Output projection
    {
        dim3 grid(CC / GBN, MM / GBM);
        gemm_tf32_kernel<<<grid, 256>>>(att, woutT, b_out, out, MM, CC, CC);
    }
}